// round 2
// baseline (speedup 1.0000x reference)
#include <cuda_runtime.h>
#include <cmath>
#include <cstdint>

static constexpr int H = 512, W = 512, BATCH = 8;
static constexpr int NPIX = H * W;
static constexpr int NXi = BATCH * 3 * NPIX;          // 6,291,456
static constexpr int NFEAT = BATCH * 32 * NPIX;       // 67,108,864
static constexpr int MAXB = 11;                       // max possible int(b) is 10
static constexpr int RBLOCKS = 512;

// Scratch feature maps (device globals per harness allocation rules)
__device__ float g_x1[NFEAT];
__device__ float g_x2[NFEAT];
__device__ float g_x3[NFEAT];
__device__ float g_part[RBLOCKS];
__device__ float g_sum[MAXB + 1];
__device__ float g_n3;
__device__ int   g_b;

// ---------------------------------------------------------------------------
// Deterministic 2-stage mean reduction. it = -1 -> unconditional (initial x).
// ---------------------------------------------------------------------------
__global__ void reduce1_k(const float* __restrict__ x, int it) {
    if (it >= 0 && it >= g_b) return;
    const float4* x4 = reinterpret_cast<const float4*>(x);
    const int n4 = NXi / 4;
    float s = 0.f;
    for (int i = blockIdx.x * 256 + threadIdx.x; i < n4; i += gridDim.x * 256) {
        float4 v = x4[i];
        s += (v.x + v.y) + (v.z + v.w);
    }
#pragma unroll
    for (int o = 16; o; o >>= 1) s += __shfl_xor_sync(0xffffffffu, s, o);
    __shared__ float ws[8];
    if ((threadIdx.x & 31) == 0) ws[threadIdx.x >> 5] = s;
    __syncthreads();
    if (threadIdx.x < 32) {
        s = (threadIdx.x < 8) ? ws[threadIdx.x] : 0.f;
#pragma unroll
        for (int o = 4; o; o >>= 1) s += __shfl_xor_sync(0xffffffffu, s, o);
        if (threadIdx.x == 0) g_part[blockIdx.x] = s;
    }
}

__global__ void reduce2_k(int slot, int it) {
    if (it >= 0 && it >= g_b) return;
    float s = 0.f;
    for (int i = threadIdx.x; i < RBLOCKS; i += 256) s += g_part[i];
#pragma unroll
    for (int o = 16; o; o >>= 1) s += __shfl_xor_sync(0xffffffffu, s, o);
    __shared__ float ws[8];
    if ((threadIdx.x & 31) == 0) ws[threadIdx.x >> 5] = s;
    __syncthreads();
    if (threadIdx.x == 0) {
        float t = 0.f;
#pragma unroll
        for (int i = 0; i < 8; i++) t += ws[i];
        g_sum[slot] = t;
    }
}

// Compute n3 and loop count b from mean of the original input (f64 math,
// matching the python-float host computation in the reference).
__global__ void params_k() {
    float m32 = g_sum[0] / (float)NXi;
    double xx1 = (double)m32;
    double s = xx1 * xx1;
    double n3 = -0.79 * s + 0.81 * xx1 + 1.4;
    double bf;
    if (xx1 < 0.1)       bf = -25.0 * xx1 + 10.0;
    else if (xx1 < 0.45) bf = 17.14 * s - 15.14 * xx1 + 10.0;
    else                 bf = 5.66 * s - 2.93 * xx1 + 7.2;
    g_n3 = (float)n3;
    int b = (int)bf;
    if (b > MAXB) b = MAXB;
    g_b = b;
}

// ---------------------------------------------------------------------------
// tf32 helpers
// ---------------------------------------------------------------------------
__device__ __forceinline__ unsigned f2tf(float x) {
    unsigned r;
    asm("cvt.rna.tf32.f32 %0, %1;" : "=r"(r) : "f"(x));
    return r;
}

__device__ __forceinline__ void mma8(float* c,
                                     unsigned a0, unsigned a1, unsigned a2, unsigned a3,
                                     unsigned b0, unsigned b1) {
    asm volatile(
        "mma.sync.aligned.m16n8k8.row.col.f32.tf32.tf32.f32 "
        "{%0,%1,%2,%3},{%4,%5,%6,%7},{%8,%9},{%0,%1,%2,%3};"
        : "+f"(c[0]), "+f"(c[1]), "+f"(c[2]), "+f"(c[3])
        : "r"(a0), "r"(a1), "r"(a2), "r"(a3), "r"(b0), "r"(b1));
}

// ---------------------------------------------------------------------------
// Implicit-GEMM 3x3 conv (SAME, zero pad) via tf32 mma.sync with 3-term
// precision split (hi*hi + lo*hi + hi*lo) for fp32-level accuracy.
//
// Block: 256 threads = 8 warps. Output tile: 32(x) * 4(y) pixels = M=128.
// Each warp owns a 16-pixel M-slice x COUTP columns (NTILES n8-tiles).
// K = CIN*9 (im2col in registers from a raw [CIN][6][36] smem tile).
// Weights pre-split in smem as [k][WSTR]: hi at col 0..COUTP-1, lo at
// LOOFF..LOOFF+COUTP-1 -> bank-conflict-free B fragment loads.
//
// EPI 0: relu(conv + bias) -> feature map (32 channels)
// EPI 1: 0.5*tanh(conv + bias) -> x_r (CREAL=3 channels), flags&2 = accumulate
// flags&1: input transform (1 - v) for the conv1 second branch.
// ---------------------------------------------------------------------------
template <int CIN, int NTILES, int CREAL, int EPI>
__global__ void __launch_bounds__(256, 2) conv_mma_k(
    const float* __restrict__ in0, const float* __restrict__ in1,
    const float* __restrict__ wg, const float* __restrict__ bg,
    float* __restrict__ out, int flags)
{
    constexpr int KTOT  = CIN * 9;
    constexpr int NSL   = (KTOT + 7) / 8;
    constexpr int KPAD  = NSL * 8;
    constexpr int COUTP = NTILES * 8;
    constexpr int WSTR  = (NTILES == 4) ? 72 : 24;
    constexpr int LOOFF = (NTILES == 4) ? 32 : 8;

    extern __shared__ float sm[];
    float* w_s  = sm;                  // KPAD * WSTR
    float* tile = sm + KPAD * WSTR;    // CIN * 6 * 36

    const int t  = threadIdx.x;
    const int bx = blockIdx.x << 5;
    const int by = blockIdx.y << 2;
    const int bb = blockIdx.z;

    // Stage pre-split weights: gmem layout wg[cout][cin*9 + ky*3 + kx]
    for (int i = t; i < KPAD * COUTP; i += 256) {
        int cout = i / KPAD, k = i - cout * KPAD;
        float v = 0.f;
        if (k < KTOT && cout < CREAL) v = wg[cout * KTOT + k];
        unsigned hi = f2tf(v);
        float lo = v - __uint_as_float(hi);
        w_s[k * WSTR + cout]          = __uint_as_float(hi);
        w_s[k * WSTR + LOOFF + cout]  = __uint_as_float(f2tf(lo));
    }

    // Stage raw input tile: CIN x 6 rows x 34 cols (stride 36), halo of 1.
    const bool inv = (flags & 1);
    for (int i = t; i < CIN * 204; i += 256) {
        int cin = i / 204, rem = i - cin * 204;
        int r = rem / 34, c = rem - r * 34;
        int gy = by - 1 + r, gx = bx - 1 + c;
        float v = 0.f;
        if ((unsigned)gy < (unsigned)H && (unsigned)gx < (unsigned)W) {
            const float* p;
            if (CIN == 64)
                p = (cin < 32) ? in0 + ((size_t)(bb * 32 + cin)) * NPIX
                               : in1 + ((size_t)(bb * 32 + cin - 32)) * NPIX;
            else
                p = in0 + ((size_t)(bb * CIN + cin)) * NPIX;
            v = p[gy * W + gx];
            if (inv) v = 1.0f - v;
        }
        tile[cin * 216 + r * 36 + c] = v;
    }
    __syncthreads();

    const int lane = t & 31, warp = t >> 5;
    const int gid = lane >> 2, tig = lane & 3;
    const int pa = warp * 16 + gid, pb = pa + 8;   // the warp's two M-rows
    const int ya = pa >> 5, xa = pa & 31;
    const int yb = pb >> 5, xb = pb & 31;

    float acc[NTILES][4];
#pragma unroll
    for (int n = 0; n < NTILES; n++) {
        acc[n][0] = acc[n][1] = acc[n][2] = acc[n][3] = 0.f;
    }

#pragma unroll 2
    for (int s = 0; s < NSL; s++) {
        const int k0 = s * 8 + tig, k1 = k0 + 4;
        float ra0 = 0.f, ra1 = 0.f, ra2 = 0.f, ra3 = 0.f;
        {
            int cin = k0 / 9, tap = k0 - cin * 9;
            int ky = tap / 3, kx = tap - ky * 3;
            int base = cin * 216 + kx;
            if (KPAD == KTOT || k0 < KTOT) {
                ra0 = tile[base + (ya + ky) * 36 + xa];
                ra1 = tile[base + (yb + ky) * 36 + xb];
            }
        }
        {
            int cin = k1 / 9, tap = k1 - cin * 9;
            int ky = tap / 3, kx = tap - ky * 3;
            int base = cin * 216 + kx;
            if (KPAD == KTOT || k1 < KTOT) {
                ra2 = tile[base + (ya + ky) * 36 + xa];
                ra3 = tile[base + (yb + ky) * 36 + xb];
            }
        }
        unsigned ah0 = f2tf(ra0), ah1 = f2tf(ra1), ah2 = f2tf(ra2), ah3 = f2tf(ra3);
        unsigned al0 = f2tf(ra0 - __uint_as_float(ah0));
        unsigned al1 = f2tf(ra1 - __uint_as_float(ah1));
        unsigned al2 = f2tf(ra2 - __uint_as_float(ah2));
        unsigned al3 = f2tf(ra3 - __uint_as_float(ah3));

        const float* wr0 = &w_s[k0 * WSTR];
        const float* wr1 = &w_s[k1 * WSTR];
#pragma unroll
        for (int n = 0; n < NTILES; n++) {
            int col = n * 8 + gid;
            unsigned bh0 = __float_as_uint(wr0[col]);
            unsigned bh1 = __float_as_uint(wr1[col]);
            unsigned bl0 = __float_as_uint(wr0[LOOFF + col]);
            unsigned bl1 = __float_as_uint(wr1[LOOFF + col]);
            mma8(acc[n], ah0, ah1, ah2, ah3, bh0, bh1);
            mma8(acc[n], al0, al1, al2, al3, bh0, bh1);
            mma8(acc[n], ah0, ah1, ah2, ah3, bl0, bl1);
        }
    }

    // Epilogue
#pragma unroll
    for (int n = 0; n < NTILES; n++) {
#pragma unroll
        for (int j = 0; j < 4; j++) {
            int cout = n * 8 + tig * 2 + (j & 1);
            int p = (j < 2) ? pa : pb;
            int y = by + (p >> 5), x = bx + (p & 31);
            if (EPI == 0) {
                float v = acc[n][j] + bg[cout];
                out[((size_t)(bb * 32 + cout)) * NPIX + y * W + x] = fmaxf(v, 0.f);
            } else {
                if (cout < CREAL) {
                    float v = 0.5f * tanhf(acc[n][j] + bg[cout]);
                    float* o = &out[((size_t)(bb * CREAL + cout)) * NPIX + y * W + x];
                    if (flags & 2) v += *o;
                    *o = v;
                }
            }
        }
    }
}

// ---------------------------------------------------------------------------
__global__ void copy_k(float* __restrict__ dst, const float* __restrict__ src) {
    int i = blockIdx.x * 256 + threadIdx.x;
    if (i < NXi / 4)
        reinterpret_cast<float4*>(dst)[i] =
            reinterpret_cast<const float4*>(src)[i];
}

// x = x + x_r * (x*x - x) * ((0.63 - m) / (n3 - m)); no-op when it >= b.
__global__ void update_k(float* __restrict__ x, const float* __restrict__ xr, int it) {
    if (it >= g_b) return;
    float m  = g_sum[it + 1] / (float)NXi;
    float cf = (0.63f - m) / (g_n3 - m);
    int i = blockIdx.x * 256 + threadIdx.x;
    if (i >= NXi / 4) return;
    float4 xv = reinterpret_cast<float4*>(x)[i];
    float4 rv = reinterpret_cast<const float4*>(xr)[i];
    xv.x += rv.x * (xv.x * xv.x - xv.x) * cf;
    xv.y += rv.y * (xv.y * xv.y - xv.y) * cf;
    xv.z += rv.z * (xv.z * xv.z - xv.z) * cf;
    xv.w += rv.w * (xv.w * xv.w - xv.w) * cf;
    reinterpret_cast<float4*>(x)[i] = xv;
}

// ---------------------------------------------------------------------------
static constexpr int SMEM_C1 = (32 * 72 + 3 * 216) * 4;     // 11,808 B
static constexpr int SMEM_C2 = (288 * 72 + 32 * 216) * 4;   // 110,592 B
static constexpr int SMEM_C7 = (576 * 24 + 64 * 216) * 4;   // 110,592 B

extern "C" void kernel_launch(void* const* d_in, const int* in_sizes, int n_in,
                              void* d_out, int out_size)
{
    const float* x  = (const float*)d_in[0];
    const float* w1 = (const float*)d_in[1];
    const float* b1 = (const float*)d_in[2];
    const float* w2 = (const float*)d_in[3];
    const float* b2 = (const float*)d_in[4];
    const float* w3 = (const float*)d_in[5];
    const float* b3 = (const float*)d_in[6];
    const float* w7 = (const float*)d_in[7];
    const float* b7 = (const float*)d_in[8];

    float* xo = (float*)d_out;      // final x
    float* xr = xo + NXi;           // x_r

    float *px1, *px2, *px3;
    cudaGetSymbolAddress((void**)&px1, g_x1);
    cudaGetSymbolAddress((void**)&px2, g_x2);
    cudaGetSymbolAddress((void**)&px3, g_x3);

    cudaFuncSetAttribute(conv_mma_k<32, 4, 32, 0>,
                         cudaFuncAttributeMaxDynamicSharedMemorySize, SMEM_C2);
    cudaFuncSetAttribute(conv_mma_k<64, 1, 3, 1>,
                         cudaFuncAttributeMaxDynamicSharedMemorySize, SMEM_C7);

    dim3 blk(256);
    dim3 cg(16, 128, 8);     // 32x4 pixel tiles over 512x512, batch 8
    int eg = (NXi / 4 + 255) / 256;

    // b / n3 from mean of original x
    reduce1_k<<<RBLOCKS, blk>>>(x, -1);
    reduce2_k<<<1, blk>>>(0, -1);
    params_k<<<1, 1>>>();

    // Two CNN branches (x and 1-x), shared weights, averaged output
    for (int br = 0; br < 2; ++br) {
        conv_mma_k<3, 4, 32, 0><<<cg, blk, SMEM_C1>>>(x, nullptr, w1, b1, px1, br ? 1 : 0);
        conv_mma_k<32, 4, 32, 0><<<cg, blk, SMEM_C2>>>(px1, nullptr, w2, b2, px2, 0);
        conv_mma_k<32, 4, 32, 0><<<cg, blk, SMEM_C2>>>(px2, nullptr, w3, b3, px3, 0);
        conv_mma_k<64, 1, 3, 1><<<cg, blk, SMEM_C7>>>(px1, px3, w7, b7, xr, br ? 2 : 0);
    }

    // Iterative mean-feedback refinement (fixed launch count, device-guarded)
    copy_k<<<eg, blk>>>(xo, x);
    for (int it = 0; it < MAXB; ++it) {
        reduce1_k<<<RBLOCKS, blk>>>(xo, it);
        reduce2_k<<<1, blk>>>(it + 1, it);
        update_k<<<eg, blk>>>(xo, xr, it);
    }
}

// round 4
// speedup vs baseline: 1.4509x; 1.4509x over previous
#include <cuda_runtime.h>
#include <cmath>
#include <cstdint>

static constexpr int H = 512, W = 512, BATCH = 8;
static constexpr int NPIX = H * W;
static constexpr int NXi = BATCH * 3 * NPIX;          // 6,291,456
static constexpr int NFEAT = BATCH * 32 * NPIX;       // 67,108,864
static constexpr int MAXB = 11;                       // int(b) <= 10 always
static constexpr int RBLOCKS = 512;
static constexpr int UBLOCKS = 1024;

__device__ float g_x1[NFEAT];
__device__ float g_x2[NFEAT];
__device__ float g_x3[NFEAT];
__device__ float g_part[UBLOCKS];
__device__ float g_sum[MAXB + 2];
__device__ float g_n3;
__device__ int   g_b;

// ---------------------------------------------------------------------------
// f32x2 packed-FMA helpers (PTX ISA 8.6, sm_100+, no "a" feature needed)
// ---------------------------------------------------------------------------
typedef unsigned long long u64;

__device__ __forceinline__ void fma2(u64& d, u64 a, u64 b) {
    asm("fma.rn.f32x2 %0, %1, %2, %0;" : "+l"(d) : "l"(a), "l"(b));
}
__device__ __forceinline__ u64 pack2(float x, float y) {
    u64 r;
    asm("mov.b64 %0, {%1, %2};" : "=l"(r) : "f"(x), "f"(y));
    return r;
}
__device__ __forceinline__ float2 unpack2(u64 v) {
    float2 f;
    asm("mov.b64 {%0, %1}, %2;" : "=f"(f.x), "=f"(f.y) : "l"(v));
    return f;
}

// ---------------------------------------------------------------------------
// Initial mean reduction + params (proven)
// ---------------------------------------------------------------------------
__global__ void reduce1_k(const float* __restrict__ x) {
    const float4* x4 = reinterpret_cast<const float4*>(x);
    const int n4 = NXi / 4;
    float s = 0.f;
    for (int i = blockIdx.x * 256 + threadIdx.x; i < n4; i += gridDim.x * 256) {
        float4 v = x4[i];
        s += (v.x + v.y) + (v.z + v.w);
    }
#pragma unroll
    for (int o = 16; o; o >>= 1) s += __shfl_xor_sync(0xffffffffu, s, o);
    __shared__ float ws[8];
    if ((threadIdx.x & 31) == 0) ws[threadIdx.x >> 5] = s;
    __syncthreads();
    if (threadIdx.x < 32) {
        s = (threadIdx.x < 8) ? ws[threadIdx.x] : 0.f;
#pragma unroll
        for (int o = 4; o; o >>= 1) s += __shfl_xor_sync(0xffffffffu, s, o);
        if (threadIdx.x == 0) g_part[blockIdx.x] = s;
    }
}

__global__ void reduce2_k() {
    float s = 0.f;
    for (int i = threadIdx.x; i < RBLOCKS; i += 256) s += g_part[i];
#pragma unroll
    for (int o = 16; o; o >>= 1) s += __shfl_xor_sync(0xffffffffu, s, o);
    __shared__ float ws[8];
    if ((threadIdx.x & 31) == 0) ws[threadIdx.x >> 5] = s;
    __syncthreads();
    if (threadIdx.x == 0) {
        float t = 0.f;
#pragma unroll
        for (int i = 0; i < 8; i++) t += ws[i];
        g_sum[0] = t;
    }
}

__global__ void params_k() {
    float m32 = g_sum[0] / (float)NXi;
    double xx1 = (double)m32;
    double s = xx1 * xx1;
    double n3 = -0.79 * s + 0.81 * xx1 + 1.4;
    double bf;
    if (xx1 < 0.1)       bf = -25.0 * xx1 + 10.0;
    else if (xx1 < 0.45) bf = 17.14 * s - 15.14 * xx1 + 10.0;
    else                 bf = 5.66 * s - 2.93 * xx1 + 7.2;
    g_n3 = (float)n3;
    int b = (int)bf;
    if (b > MAXB) b = MAXB;
    g_b = b;
}

// ---------------------------------------------------------------------------
// Main 3x3 conv (SAME, zero pad), COUT=32, relu, via packed f32x2 FMA.
// Block 256 thr = 8 warps. Tile 64x * 8y pixels. Warp: cout group (w>>1, 8
// couts as 4 float2 pairs) x 256 pixels (rows (w&1)*4 + lane/8; 8 px in x).
// Weights in smem [cin][tap][32] -> LDS.64 float2 pairs, warp-uniform.
// Activations duplicated into both f32x2 halves via mov.b64.
// flags&1: input transform v -> 1-v (conv1, branch 2).
// ---------------------------------------------------------------------------
template <int CIN>
__global__ void __launch_bounds__(256, 2) convA_k(
    const float* __restrict__ in, const float* __restrict__ wg,
    const float* __restrict__ bg, float* __restrict__ out, int flags)
{
    constexpr int WS = CIN * 9 * 32;
    __shared__ float w_s[WS];
    __shared__ float tile[10 * 68];    // 10 rows x 66 used cols, stride 68

    const int t = threadIdx.x, w = t >> 5, lane = t & 31;
    const int cg = w >> 1;                       // cout group 0..3
    const int row = ((w & 1) << 2) + (lane >> 3);  // 0..7
    const int x0 = (lane & 7) << 3;              // 0..56
    const int bx = blockIdx.x << 6, by = blockIdx.y << 3, bb = blockIdx.z;

    for (int i = t; i < WS; i += 256) {
        int cout = i & 31, rem = i >> 5;
        int cin = rem / 9, tap = rem - cin * 9;
        w_s[cin * 288 + tap * 32 + cout] = wg[(cout * CIN + cin) * 9 + tap];
    }

    u64 acc[4][8];
#pragma unroll
    for (int cp = 0; cp < 4; cp++)
#pragma unroll
        for (int p = 0; p < 8; p++) acc[cp][p] = 0ull;

    const bool inv = (flags & 1);
    const float* inb = in + (size_t)bb * CIN * NPIX;

#pragma unroll 1
    for (int cin = 0; cin < CIN; ++cin) {
        __syncthreads();
        const float* ip = inb + (size_t)cin * NPIX;
        for (int i = t; i < 660; i += 256) {
            int r = i / 66, c = i - r * 66;
            int gy = by - 1 + r, gx = bx - 1 + c;
            float v = 0.f;
            if ((unsigned)gy < (unsigned)H && (unsigned)gx < (unsigned)W) {
                v = ip[gy * W + gx];
                if (inv) v = 1.0f - v;
            }
            tile[r * 68 + c] = v;
        }
        __syncthreads();

        const float* wc = &w_s[cin * 288 + cg * 8];
#pragma unroll
        for (int ky = 0; ky < 3; ++ky) {
            const float* trp = &tile[(row + ky) * 68 + x0];
            float4 va = *reinterpret_cast<const float4*>(trp);
            float4 vb = *reinterpret_cast<const float4*>(trp + 4);
            float v8 = trp[8], v9 = trp[9];
            u64 a2[10];
            a2[0] = pack2(va.x, va.x); a2[1] = pack2(va.y, va.y);
            a2[2] = pack2(va.z, va.z); a2[3] = pack2(va.w, va.w);
            a2[4] = pack2(vb.x, vb.x); a2[5] = pack2(vb.y, vb.y);
            a2[6] = pack2(vb.z, vb.z); a2[7] = pack2(vb.w, vb.w);
            a2[8] = pack2(v8, v8);     a2[9] = pack2(v9, v9);
#pragma unroll
            for (int kx = 0; kx < 3; ++kx) {
                const float* wp = wc + (ky * 3 + kx) * 32;
                u64 w0 = *reinterpret_cast<const u64*>(wp + 0);
                u64 w1 = *reinterpret_cast<const u64*>(wp + 2);
                u64 w2 = *reinterpret_cast<const u64*>(wp + 4);
                u64 w3 = *reinterpret_cast<const u64*>(wp + 6);
#pragma unroll
                for (int p = 0; p < 8; ++p) {
                    fma2(acc[0][p], a2[p + kx], w0);
                    fma2(acc[1][p], a2[p + kx], w1);
                    fma2(acc[2][p], a2[p + kx], w2);
                    fma2(acc[3][p], a2[p + kx], w3);
                }
            }
        }
    }

    // Epilogue: bias + relu, 2 float4 stores per cout
    const size_t obase = ((size_t)bb * 32 + cg * 8) * NPIX
                       + (size_t)(by + row) * W + bx + x0;
#pragma unroll
    for (int cp = 0; cp < 4; ++cp) {
        float2 f[8];
#pragma unroll
        for (int p = 0; p < 8; ++p) f[p] = unpack2(acc[cp][p]);
        float blo = __ldg(&bg[cg * 8 + 2 * cp]);
        float bhi = __ldg(&bg[cg * 8 + 2 * cp + 1]);
        float4 lo0 = make_float4(fmaxf(f[0].x + blo, 0.f), fmaxf(f[1].x + blo, 0.f),
                                 fmaxf(f[2].x + blo, 0.f), fmaxf(f[3].x + blo, 0.f));
        float4 lo1 = make_float4(fmaxf(f[4].x + blo, 0.f), fmaxf(f[5].x + blo, 0.f),
                                 fmaxf(f[6].x + blo, 0.f), fmaxf(f[7].x + blo, 0.f));
        float4 hi0 = make_float4(fmaxf(f[0].y + bhi, 0.f), fmaxf(f[1].y + bhi, 0.f),
                                 fmaxf(f[2].y + bhi, 0.f), fmaxf(f[3].y + bhi, 0.f));
        float4 hi1 = make_float4(fmaxf(f[4].y + bhi, 0.f), fmaxf(f[5].y + bhi, 0.f),
                                 fmaxf(f[6].y + bhi, 0.f), fmaxf(f[7].y + bhi, 0.f));
        float* o0 = out + obase + (size_t)(2 * cp) * NPIX;
        float* o1 = o0 + NPIX;
        *reinterpret_cast<float4*>(o0)     = lo0;
        *reinterpret_cast<float4*>(o0 + 4) = lo1;
        *reinterpret_cast<float4*>(o1)     = hi0;
        *reinterpret_cast<float4*>(o1 + 4) = hi1;
    }
}

// ---------------------------------------------------------------------------
// conv7: cin=64 (concat x1,x3), cout=3 (padded to 4), 0.5*tanh epilogue.
// Block 256 thr; tile 64x * 32y; warp w rows w*4 + lane/8.
// flags&2: accumulate into output (branch averaging).
// ---------------------------------------------------------------------------
__global__ void __launch_bounds__(256, 2) conv7_k(
    const float* __restrict__ x1, const float* __restrict__ x3,
    const float* __restrict__ wg, const float* __restrict__ bg,
    float* __restrict__ out, int flags)
{
    __shared__ float w_s[64 * 9 * 4];
    __shared__ float tile[34 * 68];

    const int t = threadIdx.x, w = t >> 5, lane = t & 31;
    const int row = (w << 2) + (lane >> 3);      // 0..31
    const int x0 = (lane & 7) << 3;
    const int bx = blockIdx.x << 6, by = blockIdx.y << 5, bb = blockIdx.z;

    for (int i = t; i < 64 * 9 * 4; i += 256) {
        int c4 = i & 3, rem = i >> 2;
        int cin = rem / 9, tap = rem - cin * 9;
        w_s[(cin * 9 + tap) * 4 + c4] =
            (c4 < 3) ? wg[(c4 * 64 + cin) * 9 + tap] : 0.f;
    }

    u64 acc[2][8];
#pragma unroll
    for (int cp = 0; cp < 2; cp++)
#pragma unroll
        for (int p = 0; p < 8; p++) acc[cp][p] = 0ull;

#pragma unroll 1
    for (int cin = 0; cin < 64; ++cin) {
        const float* ip = (cin < 32)
            ? x1 + ((size_t)(bb * 32 + cin)) * NPIX
            : x3 + ((size_t)(bb * 32 + cin - 32)) * NPIX;
        __syncthreads();
        for (int i = t; i < 34 * 66; i += 256) {
            int r = i / 66, c = i - r * 66;
            int gy = by - 1 + r, gx = bx - 1 + c;
            tile[r * 68 + c] =
                ((unsigned)gy < (unsigned)H && (unsigned)gx < (unsigned)W)
                    ? ip[gy * W + gx] : 0.f;
        }
        __syncthreads();

        const float* wc = &w_s[cin * 36];
#pragma unroll
        for (int ky = 0; ky < 3; ++ky) {
            const float* trp = &tile[(row + ky) * 68 + x0];
            float4 va = *reinterpret_cast<const float4*>(trp);
            float4 vb = *reinterpret_cast<const float4*>(trp + 4);
            float v8 = trp[8], v9 = trp[9];
            u64 a2[10];
            a2[0] = pack2(va.x, va.x); a2[1] = pack2(va.y, va.y);
            a2[2] = pack2(va.z, va.z); a2[3] = pack2(va.w, va.w);
            a2[4] = pack2(vb.x, vb.x); a2[5] = pack2(vb.y, vb.y);
            a2[6] = pack2(vb.z, vb.z); a2[7] = pack2(vb.w, vb.w);
            a2[8] = pack2(v8, v8);     a2[9] = pack2(v9, v9);
#pragma unroll
            for (int kx = 0; kx < 3; ++kx) {
                const float* wp = wc + (ky * 3 + kx) * 4;
                u64 w0 = *reinterpret_cast<const u64*>(wp + 0);
                u64 w1 = *reinterpret_cast<const u64*>(wp + 2);
#pragma unroll
                for (int p = 0; p < 8; ++p) {
                    fma2(acc[0][p], a2[p + kx], w0);
                    fma2(acc[1][p], a2[p + kx], w1);
                }
            }
        }
    }

    const int y = by + row, xg = bx + x0;
    float b0 = __ldg(&bg[0]), b1 = __ldg(&bg[1]), b2 = __ldg(&bg[2]);
#pragma unroll
    for (int half = 0; half < 2; ++half) {
        float4 c0, c1, c2;
        float* pc0 = &c0.x; float* pc1 = &c1.x; float* pc2 = &c2.x;
#pragma unroll
        for (int j = 0; j < 4; ++j) {
            int p = half * 4 + j;
            float2 fa = unpack2(acc[0][p]);
            float2 fb = unpack2(acc[1][p]);
            pc0[j] = 0.5f * tanhf(fa.x + b0);
            pc1[j] = 0.5f * tanhf(fa.y + b1);
            pc2[j] = 0.5f * tanhf(fb.x + b2);
        }
        float* o0 = &out[((size_t)(bb * 3 + 0)) * NPIX + (size_t)y * W + xg + half * 4];
        float* o1 = &out[((size_t)(bb * 3 + 1)) * NPIX + (size_t)y * W + xg + half * 4];
        float* o2 = &out[((size_t)(bb * 3 + 2)) * NPIX + (size_t)y * W + xg + half * 4];
        if (flags & 2) {
            float4 p0 = *reinterpret_cast<float4*>(o0);
            float4 p1 = *reinterpret_cast<float4*>(o1);
            float4 p2 = *reinterpret_cast<float4*>(o2);
            c0.x += p0.x; c0.y += p0.y; c0.z += p0.z; c0.w += p0.w;
            c1.x += p1.x; c1.y += p1.y; c1.z += p1.z; c1.w += p1.w;
            c2.x += p2.x; c2.y += p2.y; c2.z += p2.z; c2.w += p2.w;
        }
        *reinterpret_cast<float4*>(o0) = c0;
        *reinterpret_cast<float4*>(o1) = c1;
        *reinterpret_cast<float4*>(o2) = c2;
    }
}

// ---------------------------------------------------------------------------
// Fused refinement update: applies x += x_r*(x^2-x)*cf and emits block
// partial sums of the NEW x (feeds next iteration's mean). it==0 also
// copies from the original input. Early-out when iteration inactive.
// ---------------------------------------------------------------------------
__global__ void update_k(const float4* __restrict__ xin, float4* __restrict__ x,
                         const float4* __restrict__ xr, int it, int first)
{
    const bool active = it < g_b;
    if (!active && !first) return;
    float m  = g_sum[it] * (1.0f / (float)NXi);
    float cf = (0.63f - m) / (g_n3 - m);
    const int n4 = NXi / 4;
    float s = 0.f;
    for (int i = blockIdx.x * 512 + threadIdx.x; i < n4; i += gridDim.x * 512) {
        float4 xv = first ? xin[i] : x[i];
        if (active) {
            float4 rv = xr[i];
            xv.x += rv.x * (xv.x * xv.x - xv.x) * cf;
            xv.y += rv.y * (xv.y * xv.y - xv.y) * cf;
            xv.z += rv.z * (xv.z * xv.z - xv.z) * cf;
            xv.w += rv.w * (xv.w * xv.w - xv.w) * cf;
            x[i] = xv;
        } else {
            x[i] = xv;   // first && !active: plain copy
        }
        s += (xv.x + xv.y) + (xv.z + xv.w);
    }
#pragma unroll
    for (int o = 16; o; o >>= 1) s += __shfl_xor_sync(0xffffffffu, s, o);
    __shared__ float ws[16];
    if ((threadIdx.x & 31) == 0) ws[threadIdx.x >> 5] = s;
    __syncthreads();
    if (threadIdx.x < 32) {
        s = (threadIdx.x < 16) ? ws[threadIdx.x] : 0.f;
#pragma unroll
        for (int o = 8; o; o >>= 1) s += __shfl_xor_sync(0xffffffffu, s, o);
        if (threadIdx.x == 0) g_part[blockIdx.x] = s;
    }
}

__global__ void finalize_k(int it) {
    if (it >= g_b) return;
    float s = 0.f;
    for (int i = threadIdx.x; i < UBLOCKS; i += 256) s += g_part[i];
#pragma unroll
    for (int o = 16; o; o >>= 1) s += __shfl_xor_sync(0xffffffffu, s, o);
    __shared__ float ws[8];
    if ((threadIdx.x & 31) == 0) ws[threadIdx.x >> 5] = s;
    __syncthreads();
    if (threadIdx.x == 0) {
        float t = 0.f;
#pragma unroll
        for (int i = 0; i < 8; i++) t += ws[i];
        g_sum[it + 1] = t;
    }
}

// ---------------------------------------------------------------------------
extern "C" void kernel_launch(void* const* d_in, const int* in_sizes, int n_in,
                              void* d_out, int out_size)
{
    const float* x  = (const float*)d_in[0];
    const float* w1 = (const float*)d_in[1];
    const float* b1 = (const float*)d_in[2];
    const float* w2 = (const float*)d_in[3];
    const float* b2 = (const float*)d_in[4];
    const float* w3 = (const float*)d_in[5];
    const float* b3 = (const float*)d_in[6];
    const float* w7 = (const float*)d_in[7];
    const float* b7 = (const float*)d_in[8];

    float* xo = (float*)d_out;      // final x
    float* xr = xo + NXi;           // x_r

    float *px1, *px2, *px3;
    cudaGetSymbolAddress((void**)&px1, g_x1);
    cudaGetSymbolAddress((void**)&px2, g_x2);
    cudaGetSymbolAddress((void**)&px3, g_x3);

    dim3 blk(256);
    dim3 cga(8, 64, 8);      // 64x * 8y tiles
    dim3 cg7(8, 16, 8);      // 64x * 32y tiles

    reduce1_k<<<RBLOCKS, blk>>>(x);
    reduce2_k<<<1, blk>>>();
    params_k<<<1, 1>>>();

    for (int br = 0; br < 2; ++br) {
        convA_k<3><<<cga, blk>>>(x, w1, b1, px1, br ? 1 : 0);
        convA_k<32><<<cga, blk>>>(px1, w2, b2, px2, 0);
        convA_k<32><<<cga, blk>>>(px2, w3, b3, px3, 0);
        conv7_k<<<cg7, blk>>>(px1, px3, w7, b7, xr, br ? 2 : 0);
    }

    for (int it = 0; it < MAXB; ++it) {
        update_k<<<UBLOCKS, 512>>>((const float4*)x, (float4*)xo,
                                   (const float4*)xr, it, it == 0 ? 1 : 0);
        finalize_k<<<1, blk>>>(it);
    }
}